// round 10
// baseline (speedup 1.0000x reference)
#include <cuda_runtime.h>

#define NFFT 16384
#define THREADS 512
#define PI_F 3.14159265358979323846f
#define SQRT_HALF 0.70710678118654752440f

// Inverse-FFT radix-16 twiddles: W_16^j = e^{+j*2*pi*j/16}, j=0..7
__constant__ float C16[8] = {
    1.0f, 0.92387953251128675613f, 0.70710678118654752440f, 0.38268343236508977173f,
    0.0f,-0.38268343236508977173f,-0.70710678118654752440f,-0.92387953251128675613f };
__constant__ float S16[8] = {
    0.0f, 0.38268343236508977173f, 0.70710678118654752440f, 0.92387953251128675613f,
    1.0f, 0.92387953251128675613f, 0.70710678118654752440f, 0.38268343236508977173f };

struct cplx { float x, y; };

__device__ __forceinline__ cplx padd(cplx a, cplx b) {
    cplx r;
    asm("{\n\t.reg .b64 ra, rb, rr;\n\t"
        "mov.b64 ra, {%2, %3};\n\tmov.b64 rb, {%4, %5};\n\t"
        "add.rn.f32x2 rr, ra, rb;\n\tmov.b64 {%0, %1}, rr;\n\t}"
        : "=f"(r.x), "=f"(r.y) : "f"(a.x), "f"(a.y), "f"(b.x), "f"(b.y));
    return r;
}
__device__ __forceinline__ cplx psub(cplx a, cplx b, unsigned long long neg1) {
    cplx r;
    asm("{\n\t.reg .b64 ra, rb, rr;\n\t"
        "mov.b64 ra, {%2, %3};\n\tmov.b64 rb, {%4, %5};\n\t"
        "fma.rn.f32x2 rr, rb, %6, ra;\n\tmov.b64 {%0, %1}, rr;\n\t}"
        : "=f"(r.x), "=f"(r.y) : "f"(a.x), "f"(a.y), "f"(b.x), "f"(b.y), "l"(neg1));
    return r;
}

// In-place DIF radix-16 inverse FFT (e^{+j}). Natural in, digit-reversed out.
__device__ __forceinline__ void fft16_inv(cplx* r, unsigned long long neg1) {
    #pragma unroll
    for (int half = 8; half >= 1; half >>= 1) {
        #pragma unroll
        for (int base = 0; base < 16; base += 2 * half) {
            #pragma unroll
            for (int j = 0; j < half; j++) {
                cplx a = r[base + j];
                cplx b = r[base + half + j];
                r[base + j] = padd(a, b);
                cplx d = psub(a, b, neg1);
                const int tw = j * (8 / half);
                if (tw == 0)      { r[base+half+j] = d; }
                else if (tw == 4) { r[base+half+j].x = -d.y; r[base+half+j].y = d.x; }
                else {
                    float c = C16[tw], s = S16[tw];
                    r[base+half+j].x = d.x * c - d.y * s;
                    r[base+half+j].y = d.x * s + d.y * c;
                }
            }
        }
    }
}

// Slot layout: F[4096] float4 slots; logical position pi -> slot pi ^ ((pi>>8)&15).
// Slot holds two float2 halves (A,B): A at f2[2*sl + ha], B at f2[2*sl + 1-ha],
// ha = bit3 of slot low digit (de-conflicts 16-lane LDS.64 phases).
__device__ __forceinline__ int slotof(int pi) { return pi ^ ((pi >> 8) & 15); }

__global__ void __launch_bounds__(THREADS, 2)
idxct_kernel(const float* __restrict__ x, float* __restrict__ y)
{
    extern __shared__ float smem[];
    float2* f2  = (float2*)smem;
    float4* f4p = (float4*)smem;

    const int row = blockIdx.x;
    const int t   = threadIdx.x;

    unsigned long long NEG1;
    asm("mov.b64 %0, 0xBF800000BF800000;" : "=l"(NEG1));

    const int REV4[16] = {0,8,4,12,2,10,6,14,1,9,5,13,3,11,7,15};

    // ---- Phase 0: stage x as pairs. Slot v holds (x[2v],x[2v+8192] | x[2v+1],x[2v+8193]).
    {
        const float4* x4 = (const float4*)(x + (size_t)row * NFFT);
        #pragma unroll
        for (int j = 0; j < 8; j++) {
            int v = t + THREADS * j;
            float4 a = x4[v >> 1];              // lane pairs dedup in coalescer
            float4 b = x4[(v >> 1) + 2048];
            int rs = v & 1;
            float xl0 = rs ? a.z : a.x, xl1 = rs ? a.w : a.y;
            float xh0 = rs ? b.z : b.x, xh1 = rs ? b.w : b.y;
            int sl = slotof(v);
            int ha = (sl >> 3) & 1;
            f4p[sl] = ha ? make_float4(xl1, xh1, xl0, xh0)
                         : make_float4(xl0, xh0, xl1, xh1);
        }
    }
    __syncthreads();

    // ---- Phase 1a: spectrum q_m in-place over pair slots (conjugate-pair trick).
    {
        const float cD = 0.99518472667219688624f;   // cos(pi/32)  (u step = 512)
        const float sD = 0.09801714032956060199f;   // sin(pi/32)

        // A tasks: u = n1*512 + t (n1=0..3), m = 2u even, partner u' = 4096-u.
        float cb, sb;
        __sincosf((float)(2 * t) * (PI_F / 32768.0f), &sb, &cb);
        #pragma unroll
        for (int n1 = 0; n1 < 4; n1++) {
            int u = n1 * 512 + t;
            if (u == 0) {
                float2 P = f2[0];                  // slot 0, ha=0 -> A at offset 0
                float ux = 2.0f * P.x + 2.0f * SQRT_HALF * P.y;
                float vx = 2.0f * P.x - 2.0f * SQRT_HALF * P.y;
                f2[0] = make_float2(0.5f * ux, 0.5f * vx);
                {   // q_2048 (m=4096, self-partner)
                    const float c8 = 0.92387953251128675613f;  // cos(pi/8)
                    const float s8 = 0.38268343236508977173f;  // sin(pi/8)
                    int sl2 = slotof(2048);
                    int ha2 = (sl2 >> 3) & 1;
                    float2 P2 = f2[2 * sl2 + ha2];
                    float e2x = (c8 - s8) * SQRT_HALF, e2y = (c8 + s8) * SQRT_HALF;
                    float t2x = 2.0f * e2x * e2y, t2y = 2.0f * c8 * s8;
                    float tx = t2x * t2x - t2y * t2y, ty = 2.0f * t2x * t2y;
                    float s1x = P2.x * c8 + P2.y * s8, s1y = P2.x * s8 - P2.y * c8;
                    float s2x = P2.y * e2x + P2.x * e2y, s2y = P2.y * e2y - P2.x * e2x;
                    float ux2 = s1x + s2x, uy2 = s1y + s2y;
                    float vx2 = s1x - s2x, vy2 = s1y - s2y;
                    float gx = tx * vy2 + ty * vx2, gy = tx * vx2 - ty * vy2;
                    f2[2 * sl2 + ha2] = make_float2(0.5f * (ux2 - gx), 0.5f * (uy2 + gy));
                }
            } else {
                int up = 4096 - u;
                int slu = slotof(u),  hau = (slu >> 3) & 1;
                int slp = slotof(up), hap = (slp >> 3) & 1;
                float2 P = f2[2 * slu + hau];   // (x_m, x_{m+8192})
                float2 Q = f2[2 * slp + hap];   // (x_{8192-m}, x_{16384-m})
                float e2x = (cb - sb) * SQRT_HALF, e2y = (cb + sb) * SQRT_HALF;
                float t2x = 2.0f * e2x * e2y, t2y = 2.0f * cb * sb;
                float tx = t2x * t2x - t2y * t2y, ty = 2.0f * t2x * t2y;
                float s1x = P.x * cb + Q.y * sb,  s1y = P.x * sb - Q.y * cb;
                float s2x = P.y * e2x + Q.x * e2y, s2y = P.y * e2y - Q.x * e2x;
                float ux = s1x + s2x, uy = s1y + s2y;
                float vx = s1x - s2x, vy = s1y - s2y;
                float gx = tx * vy + ty * vx, gy = tx * vx - ty * vy;
                f2[2 * slu + hau] = make_float2(0.5f * (ux - gx), 0.5f * (uy + gy));
                f2[2 * slp + hap] = make_float2(0.5f * (ux + gx), 0.5f * (gy - uy));
            }
            float ncb = cb * cD - sb * sD;
            sb = sb * cD + cb * sD;
            cb = ncb;
        }

        // B tasks: m = 2u+1 odd, partner u' = 4095-u. All proper pairs.
        __sincosf((float)(2 * t + 1) * (PI_F / 32768.0f), &sb, &cb);
        #pragma unroll
        for (int n1 = 0; n1 < 4; n1++) {
            int u = n1 * 512 + t;
            int up = 4095 - u;
            int slu = slotof(u),  hau = (slu >> 3) & 1;
            int slp = slotof(up), hap = (slp >> 3) & 1;
            float2 P = f2[2 * slu + (hau ^ 1)];
            float2 Q = f2[2 * slp + (hap ^ 1)];
            float e2x = (cb - sb) * SQRT_HALF, e2y = (cb + sb) * SQRT_HALF;
            float t2x = 2.0f * e2x * e2y, t2y = 2.0f * cb * sb;
            float tx = t2x * t2x - t2y * t2y, ty = 2.0f * t2x * t2y;
            float s1x = P.x * cb + Q.y * sb,  s1y = P.x * sb - Q.y * cb;
            float s2x = P.y * e2x + Q.x * e2y, s2y = P.y * e2y - Q.x * e2x;
            float ux = s1x + s2x, uy = s1y + s2y;
            float vx = s1x - s2x, vy = s1y - s2y;
            float gx = tx * vy + ty * vx, gy = tx * vx - ty * vy;
            f2[2 * slu + (hau ^ 1)] = make_float2(0.5f * (ux - gx), 0.5f * (uy + gy));
            f2[2 * slp + (hap ^ 1)] = make_float2(0.5f * (ux + gx), 0.5f * (gy - uy));
            float ncb = cb * cD - sb * sD;
            sb = sb * cD + cb * sD;
            cb = ncb;
        }
    }
    __syncthreads();

    // ---- Pass 1: radix-16 over n1, twiddle W_4096^{+tp*k1}. One chunk per thread.
    {
        const int h  = t >> 8;          // which half (A=0 / B=1)
        const int tp = t & 255;
        float w1c, w1s;
        __sincosf((float)tp * (2.0f * PI_F / 4096.0f), &w1s, &w1c);
        cplx r[16];
        #pragma unroll
        for (int n1 = 0; n1 < 16; n1++) {
            int sl = (n1 * 256 + tp) ^ n1;
            float2 v = f2[2 * sl + ((((sl >> 3) & 1)) ^ h)];
            r[n1].x = v.x; r[n1].y = v.y;
        }
        fft16_inv(r, NEG1);
        float wc = 1.0f, ws = 0.0f;
        #pragma unroll
        for (int k1 = 0; k1 < 16; k1++) {
            const int i = REV4[k1];
            float vx = r[i].x * wc - r[i].y * ws;
            float vy = r[i].x * ws + r[i].y * wc;
            int sl = (k1 * 256 + tp) ^ k1;
            f2[2 * sl + ((((sl >> 3) & 1)) ^ h)] = make_float2(vx, vy);
            float nwc = wc * w1c - ws * w1s;
            ws = ws * w1c + wc * w1s;
            wc = nwc;
        }
    }
    __syncthreads();

    // ---- Pass 2: radix-16 over middle digit, twiddle W_256^{+b*k2}.
    {
        const int h  = t >> 8;
        const int th = t & 255;
        const int k1 = th & 15;
        const int b  = th >> 4;
        float w2c, w2s;
        __sincosf((float)b * (PI_F / 128.0f), &w2s, &w2c);
        const int slbase = (k1 << 8) + (b ^ k1);
        const int off = ((((b ^ k1) >> 3) & 1) ^ h);
        cplx r[16];
        #pragma unroll
        for (int a = 0; a < 16; a++) {
            float2 v = f2[2 * (slbase + a * 16) + off];
            r[a].x = v.x; r[a].y = v.y;
        }
        fft16_inv(r, NEG1);
        float wc = 1.0f, ws = 0.0f;
        #pragma unroll
        for (int k2 = 0; k2 < 16; k2++) {
            const int i = REV4[k2];
            float vx = r[i].x * wc - r[i].y * ws;
            float vy = r[i].x * ws + r[i].y * wc;
            f2[2 * (slbase + k2 * 16) + off] = make_float2(vx, vy);
            float nwc = wc * w2c - ws * w2s;
            ws = ws * w2c + wc * w2s;
            wc = nwc;
        }
    }
    __syncthreads();

    // ---- Pass 3: radix-16 over low digit, no twiddle. One half per thread.
    {
        const int h  = t >> 8;
        const int th = t & 255;
        const int k1 = th & 15;
        const int c  = th >> 4;
        const int base0 = (k1 << 8) + (c << 4);
        cplx r[16];
        #pragma unroll
        for (int d = 0; d < 16; d++) {
            int lo = d ^ k1;
            float2 v = f2[2 * (base0 + lo) + (((lo >> 3) & 1) ^ h)];
            r[d].x = v.x; r[d].y = v.y;
        }
        fft16_inv(r, NEG1);
        #pragma unroll
        for (int i = 0; i < 16; i++) {
            int lo = REV4[i] ^ k1;
            f2[2 * (base0 + lo) + (((lo >> 3) & 1) ^ h)] = make_float2(r[i].x, r[i].y);
        }
    }
    __syncthreads();

    // ---- Gather: radix-2 combine + de-permute, contiguous float4 stores.
    // z_q        = A_q + w^q B_q,  w = e^{+j*2*pi/8192}
    // z_{8191-q} = A_{4095-q} + conj-rotated B_{4095-q} (folded via w^{q+1})
    // y[4q]=Re z_q, y[4q+1]=Im z_{8191-q}, y[4q+2]=Im z_q, y[4q+3]=Re z_{8191-q}
    {
        float4* y4 = (float4*)(y + (size_t)row * NFFT);
        const float c1 = 0.99999970586288222663f;      // cos(2*pi/8192)
        const float s1 = 7.66990318742704526939e-4f;   // sin(2*pi/8192)
        const float cS = 0.92387953251128675613f;      // cos(pi/8)   (q step = 512)
        const float sS = 0.38268343236508977173f;      // sin(pi/8)
        float wc, ws;
        __sincosf((float)t * (2.0f * PI_F / 8192.0f), &ws, &wc);
        const int d0 = t & 15, d1 = (t >> 4) & 15;
        const int baseA = (d0 << 8) + (d1 << 4);
        const int baseM = ((15 - d0) << 8) + ((15 - d1) << 4);
        #pragma unroll
        for (int jj = 0; jj < 8; jj++) {
            int qo = t + THREADS * jj;                 // [0, 4096)
            int d2 = qo >> 8;
            int loA = d2 ^ d0;
            int loM = (15 - d2) ^ (15 - d0);
            float2 A  = f2[2 * (baseA + loA) + (((loA >> 3) & 1))];
            float2 B  = f2[2 * (baseA + loA) + (((loA >> 3) & 1) ^ 1)];
            float2 M  = f2[2 * (baseM + loM) + (((loM >> 3) & 1))];
            float2 Nw = f2[2 * (baseM + loM) + (((loM >> 3) & 1) ^ 1)];
            float ox = wc * c1 - ws * s1;              // w^{q+1}
            float oy = wc * s1 + ws * c1;
            cplx wB, oN, Ac, Mc;
            wB.x = wc * B.x - ws * B.y;
            wB.y = wc * B.y + ws * B.x;
            oN.x = ox * Nw.x + oy * Nw.y;
            oN.y = ox * Nw.y - oy * Nw.x;
            Ac.x = A.x; Ac.y = A.y;
            Mc.x = M.x; Mc.y = M.y;
            cplx z1 = padd(Ac, wB);
            cplx z2 = padd(Mc, oN);
            y4[qo] = make_float4(z1.x, z2.y, z1.y, z2.x);
            float nwc = wc * cS - ws * sS;             // w *= e^{j*pi/8}
            ws = ws * cS + wc * sS;
            wc = nwc;
        }
    }
}

extern "C" void kernel_launch(void* const* d_in, const int* in_sizes, int n_in,
                              void* d_out, int out_size)
{
    const float* x = (const float*)d_in[0];
    float*       y = (float*)d_out;

    const int rows = in_sizes[0] / NFFT;
    const int smem_bytes = NFFT * (int)sizeof(float);   // 64 KB

    cudaFuncSetAttribute(idxct_kernel,
                         cudaFuncAttributeMaxDynamicSharedMemorySize, smem_bytes);

    idxct_kernel<<<rows, THREADS, smem_bytes>>>(x, y);
}